// round 1
// baseline (speedup 1.0000x reference)
#include <cuda_runtime.h>
#include <cstdint>

#define D 64
#define MAX_NODES 100000

// Scratch: support = X @ W  (25.6 MB) — static __device__ array per harness rules.
__device__ float g_support[(size_t)MAX_NODES * D];

// Kernel A: support = X @ W, and out[r][c] = bias[c] (init for scatter-add).
// Block = 256 threads = 4 rows x 64 cols per iteration. W cached in smem once
// per block (grid-stride over row groups so W is loaded ~NB times, not N/4).
__global__ void __launch_bounds__(256) gemm_bias_init(
    const float* __restrict__ x,
    const float* __restrict__ W,
    const float* __restrict__ bias,
    float* __restrict__ out,
    int N)
{
    __shared__ float Ws[D * D];
    __shared__ float xs[4][D];

    for (int i = threadIdx.x; i < D * D; i += 256) Ws[i] = W[i];

    const int c    = threadIdx.x & 63;   // output column
    const int rloc = threadIdx.x >> 6;   // local row 0..3
    const float b  = bias[c];
    __syncthreads();

    const int numGroups = (N + 3) >> 2;
    for (int g = blockIdx.x; g < numGroups; g += gridDim.x) {
        const int r0 = g << 2;
        __syncthreads();               // protect xs from previous iteration
        const int rr = r0 + rloc;
        xs[rloc][c] = (rr < N) ? x[(size_t)rr * D + c] : 0.0f;
        __syncthreads();

        const int r = r0 + rloc;
        if (r < N) {
            float acc = 0.0f;
            #pragma unroll
            for (int k = 0; k < D; ++k)
                acc = fmaf(xs[rloc][k], Ws[k * D + c], acc);
            g_support[(size_t)r * D + c] = acc;
            out[(size_t)r * D + c] = b;
        }
    }
}

// Kernel B: scatter-add messages. 16 lanes per edge; each lane handles one
// float4 of the 64-float row. Gather from g_support (L2-resident), scale by
// edge weight, reduce into out with vectorized red.global.add.v4.f32.
__global__ void __launch_bounds__(256) spmm_scatter(
    const int*   __restrict__ ei,      // [2, E]: row0 = dst, row1 = src
    const float* __restrict__ ew,      // [E]
    float* __restrict__ out,
    int E)
{
    const int i = blockIdx.x * 256 + threadIdx.x;
    const int total = E * 16;
    if (i >= total) return;

    const int e = i >> 4;
    const int l = i & 15;

    const int dst   = ei[e];
    const int src   = ei[E + e];
    const float w   = ew[e];

    const float4* s4 = reinterpret_cast<const float4*>(g_support);
    float4 v = __ldg(&s4[(size_t)src * 16 + l]);
    v.x *= w; v.y *= w; v.z *= w; v.w *= w;

    float* p = out + (size_t)dst * D + l * 4;
    asm volatile("red.global.add.v4.f32 [%0], {%1, %2, %3, %4};"
                 :: "l"(p), "f"(v.x), "f"(v.y), "f"(v.z), "f"(v.w)
                 : "memory");
}

extern "C" void kernel_launch(void* const* d_in, const int* in_sizes, int n_in,
                              void* d_out, int out_size)
{
    const float* x    = (const float*)d_in[0];   // [N, 64]
    const int*   ei   = (const int*)  d_in[1];   // [2, E]
    const float* ew   = (const float*)d_in[2];   // [E]
    const float* W    = (const float*)d_in[3];   // [64, 64]
    const float* bias = (const float*)d_in[4];   // [64]
    float* out = (float*)d_out;

    const int N = in_sizes[0] / D;
    const int E = in_sizes[2];

    // Kernel A: grid-stride, enough blocks to fill the chip a few times over.
    gemm_bias_init<<<1480, 256>>>(x, W, bias, out, N);

    // Kernel B: one thread per (edge, float4-lane).
    const long long total = (long long)E * 16;
    const int blocks = (int)((total + 255) / 256);
    spmm_scatter<<<blocks, 256>>>(ei, ew, out, E);
}

// round 3
// speedup vs baseline: 1.6923x; 1.6923x over previous
#include <cuda_runtime.h>
#include <cstdint>

#define D     64
#define MAXN  100000
#define MAXE  1600000
#define SCAN_BLK 1024

// ---------------- scratch (static __device__, per harness rules) ----------------
__device__ float g_support[(size_t)MAXN * D];   // X @ W
__device__ int   g_deg [MAXN];                  // per-dst degree
__device__ int   g_ptr [MAXN];                  // CSR row start (exclusive scan of deg)
__device__ int   g_pos [MAXN];                  // scatter cursor (mutable copy of ptr)
__device__ int   g_part[256];                   // block partial sums for scan
__device__ int2  g_csr [MAXE];                  // bucketed edges: {src, bits(w)}

// ---------------- Kernel 1: support = X @ W (register-tiled 64x64) ----------------
// Block = 256 threads = 16x16; each thread computes a 4x4 output patch.
__global__ void __launch_bounds__(256) gemm64(
    const float* __restrict__ x,
    const float* __restrict__ W,
    int N)
{
    __shared__ float Ws[D][D];
    __shared__ float xs[D][D + 1];   // +1 pad: xs[r][k] column reads ~conflict-free

    const int t  = threadIdx.x;
    const int tx = t & 15;           // -> columns c0 = 4*tx
    const int ty = t >> 4;           // -> rows    r0 = 4*ty
    const int tileRow = blockIdx.x * 64;

    // Stage W (4096 floats) via float4, straight copy (row stride 64 -> aligned).
    {
        const float4* W4 = reinterpret_cast<const float4*>(W);
        float4* Ws4 = reinterpret_cast<float4*>(&Ws[0][0]);
        #pragma unroll
        for (int i = 0; i < 4; ++i) Ws4[t + i * 256] = W4[t + i * 256];
    }
    // Stage 64 rows of x. Global read is float4; smem store MUST be scalar:
    // xs row stride is 65 floats (260 B), so float4 stores would be misaligned.
    {
        const float4* x4 = reinterpret_cast<const float4*>(x);
        #pragma unroll
        for (int i = 0; i < 4; ++i) {
            int f = t + i * 256;            // 0..1023
            int r = f >> 4, c4 = f & 15;
            int gr = tileRow + r;
            float4 v = make_float4(0.f, 0.f, 0.f, 0.f);
            if (gr < N) v = x4[(size_t)gr * 16 + c4];
            xs[r][c4 * 4 + 0] = v.x;
            xs[r][c4 * 4 + 1] = v.y;
            xs[r][c4 * 4 + 2] = v.z;
            xs[r][c4 * 4 + 3] = v.w;
        }
    }
    __syncthreads();

    float a[4][4];
    #pragma unroll
    for (int i = 0; i < 4; ++i)
        #pragma unroll
        for (int j = 0; j < 4; ++j) a[i][j] = 0.f;

    const int r0 = ty * 4, c0 = tx * 4;
    #pragma unroll
    for (int k = 0; k < D; ++k) {
        float4 wv = *reinterpret_cast<const float4*>(&Ws[k][c0]);
        float xv0 = xs[r0 + 0][k];
        float xv1 = xs[r0 + 1][k];
        float xv2 = xs[r0 + 2][k];
        float xv3 = xs[r0 + 3][k];
        a[0][0] = fmaf(xv0, wv.x, a[0][0]); a[0][1] = fmaf(xv0, wv.y, a[0][1]);
        a[0][2] = fmaf(xv0, wv.z, a[0][2]); a[0][3] = fmaf(xv0, wv.w, a[0][3]);
        a[1][0] = fmaf(xv1, wv.x, a[1][0]); a[1][1] = fmaf(xv1, wv.y, a[1][1]);
        a[1][2] = fmaf(xv1, wv.z, a[1][2]); a[1][3] = fmaf(xv1, wv.w, a[1][3]);
        a[2][0] = fmaf(xv2, wv.x, a[2][0]); a[2][1] = fmaf(xv2, wv.y, a[2][1]);
        a[2][2] = fmaf(xv2, wv.z, a[2][2]); a[2][3] = fmaf(xv2, wv.w, a[2][3]);
        a[3][0] = fmaf(xv3, wv.x, a[3][0]); a[3][1] = fmaf(xv3, wv.y, a[3][1]);
        a[3][2] = fmaf(xv3, wv.z, a[3][2]); a[3][3] = fmaf(xv3, wv.w, a[3][3]);
    }

    #pragma unroll
    for (int i = 0; i < 4; ++i) {
        int gr = tileRow + r0 + i;
        if (gr < N) {
            float4 v = make_float4(a[i][0], a[i][1], a[i][2], a[i][3]);
            reinterpret_cast<float4*>(g_support)[(size_t)gr * 16 + tx] = v;
        }
    }
}

// ---------------- Kernel 2: zero degree counters ----------------
__global__ void zero_deg(int N)
{
    int i = blockIdx.x * 256 + threadIdx.x;
    if (i < N) g_deg[i] = 0;
}

// ---------------- Kernel 3: histogram of dst ----------------
__global__ void hist_dst(const int* __restrict__ ei, int E)
{
    int e = blockIdx.x * 256 + threadIdx.x;
    if (e < E) atomicAdd(&g_deg[ei[e]], 1);   // result unused -> RED
}

// ---------------- Kernel 4a: per-block inclusive scan (1024 elems/block) -------
__global__ void __launch_bounds__(SCAN_BLK) scanA(int N)
{
    __shared__ int s[2][SCAN_BLK];
    int tid = threadIdx.x;
    int gid = blockIdx.x * SCAN_BLK + tid;
    int v = (gid < N) ? g_deg[gid] : 0;
    int buf = 0;
    s[0][tid] = v;
    __syncthreads();
    #pragma unroll
    for (int off = 1; off < SCAN_BLK; off <<= 1) {
        int t = s[buf][tid];
        if (tid >= off) t += s[buf][tid - off];
        s[buf ^ 1][tid] = t;
        buf ^= 1;
        __syncthreads();
    }
    int inc = s[buf][tid];
    if (gid < N) g_ptr[gid] = inc - v;             // exclusive within block
    if (tid == SCAN_BLK - 1) g_part[blockIdx.x] = inc;  // block total
}

// ---------------- Kernel 4b: scan block totals (single block, nb <= 128) -------
__global__ void __launch_bounds__(128) scanB(int nb)
{
    __shared__ int s[2][128];
    int tid = threadIdx.x;
    int v = (tid < nb) ? g_part[tid] : 0;
    int buf = 0;
    s[0][tid] = v;
    __syncthreads();
    #pragma unroll
    for (int off = 1; off < 128; off <<= 1) {
        int t = s[buf][tid];
        if (tid >= off) t += s[buf][tid - off];
        s[buf ^ 1][tid] = t;
        buf ^= 1;
        __syncthreads();
    }
    if (tid < nb) g_part[tid] = s[buf][tid] - v;   // exclusive block offsets
}

// ---------------- Kernel 4c: add block offsets; init cursors ----------------
__global__ void scanC(int N)
{
    int i = blockIdx.x * 256 + threadIdx.x;
    if (i < N) {
        int p = g_ptr[i] + g_part[i >> 10];
        g_ptr[i] = p;
        g_pos[i] = p;
    }
}

// ---------------- Kernel 5: bucket edges by dst ----------------
__global__ void bucket_edges(const int* __restrict__ ei,
                             const float* __restrict__ ew, int E)
{
    int e = blockIdx.x * 256 + threadIdx.x;
    if (e < E) {
        int dst = ei[e];
        int src = ei[E + e];
        float w = ew[e];
        int p = atomicAdd(&g_pos[dst], 1);
        g_csr[p] = make_int2(src, __float_as_int(w));
    }
}

// ---------------- Kernel 6: SpMM over CSR, warp per dst node ----------------
// 32 lanes, each owns a float2 (8B) of the 64-float row. No atomics: single
// coalesced write per node, fused with bias.
__global__ void __launch_bounds__(256) spmm_csr(
    const float* __restrict__ bias,
    float* __restrict__ out,
    int N)
{
    const int node = blockIdx.x * 8 + (threadIdx.x >> 5);
    const int lane = threadIdx.x & 31;
    if (node >= N) return;

    const int start = g_ptr[node];
    const int deg   = g_deg[node];
    const int end   = start + deg;

    const float2* sup2 = reinterpret_cast<const float2*>(g_support);
    float2 acc = make_float2(0.f, 0.f);

    int j = start;
    // 2-edge unroll: two independent gather chains in flight.
    for (; j + 2 <= end; j += 2) {
        int2 m0 = __ldg(&g_csr[j]);
        int2 m1 = __ldg(&g_csr[j + 1]);
        float2 v0 = __ldg(&sup2[(size_t)m0.x * 32 + lane]);
        float2 v1 = __ldg(&sup2[(size_t)m1.x * 32 + lane]);
        float w0 = __int_as_float(m0.y);
        float w1 = __int_as_float(m1.y);
        acc.x = fmaf(w0, v0.x, acc.x);
        acc.y = fmaf(w0, v0.y, acc.y);
        acc.x = fmaf(w1, v1.x, acc.x);
        acc.y = fmaf(w1, v1.y, acc.y);
    }
    if (j < end) {
        int2 m = __ldg(&g_csr[j]);
        float2 v = __ldg(&sup2[(size_t)m.x * 32 + lane]);
        float w = __int_as_float(m.y);
        acc.x = fmaf(w, v.x, acc.x);
        acc.y = fmaf(w, v.y, acc.y);
    }

    float2 b = reinterpret_cast<const float2*>(bias)[lane];
    acc.x += b.x;
    acc.y += b.y;
    reinterpret_cast<float2*>(out)[(size_t)node * 32 + lane] = acc;
}

// ---------------- launch ----------------
extern "C" void kernel_launch(void* const* d_in, const int* in_sizes, int n_in,
                              void* d_out, int out_size)
{
    const float* x    = (const float*)d_in[0];   // [N, 64]
    const int*   ei   = (const int*)  d_in[1];   // [2, E]
    const float* ew   = (const float*)d_in[2];   // [E]
    const float* W    = (const float*)d_in[3];   // [64, 64]
    const float* bias = (const float*)d_in[4];   // [64]
    float* out = (float*)d_out;

    const int N = in_sizes[0] / D;
    const int E = in_sizes[2];

    const int nb   = (N + SCAN_BLK - 1) / SCAN_BLK;   // scan blocks (98 for N=100k)
    const int gE   = (E + 255) / 256;
    const int gN   = (N + 255) / 256;

    gemm64<<<(N + 63) / 64, 256>>>(x, W, N);
    zero_deg<<<gN, 256>>>(N);
    hist_dst<<<gE, 256>>>(ei, E);
    scanA<<<nb, SCAN_BLK>>>(N);
    scanB<<<1, 128>>>(nb);
    scanC<<<gN, 256>>>(N);
    bucket_edges<<<gE, 256>>>(ei, ew, E);
    spmm_csr<<<(N + 7) / 8, 256>>>(bias, out, N);
}

// round 4
// speedup vs baseline: 1.7250x; 1.0193x over previous
#include <cuda_runtime.h>
#include <cuda_fp16.h>
#include <cstdint>

#define D     64
#define MAXN  100000
#define MAXE  1600000

// ---------------- scratch (static __device__, zero-initialized at load) --------
__device__ __align__(16) __half g_support[(size_t)MAXN * D];  // X @ W, fp16 (12.8 MB)
__device__ __align__(16) int    g_deg [MAXN];      // per-dst degree (zeroed after use)
__device__ __align__(16) int    g_ptr [MAXN + 4];  // CSR row starts + sentinel ptr[N]=E
__device__ __align__(16) int    g_pos [MAXN];      // scatter cursors
__device__              int     g_part[256];       // per-block scan partials
__device__ __align__(16) int2   g_csr [MAXE];      // bucketed edges {src, bits(w)}

// ---------------- Kernel 1: support = half(X @ W), register-tiled 64x64 --------
__global__ void __launch_bounds__(256) gemm64(
    const float* __restrict__ x,
    const float* __restrict__ W,
    int N)
{
    __shared__ float Ws[D][D];
    __shared__ float xs[D][D + 1];   // +1 pad: column reads ~conflict-free

    const int t  = threadIdx.x;
    const int tx = t & 15;           // columns c0 = 4*tx
    const int ty = t >> 4;           // rows    r0 = 4*ty
    const int tileRow = blockIdx.x * 64;

    {   // stage W via float4 (row stride 64 floats -> aligned)
        const float4* W4 = reinterpret_cast<const float4*>(W);
        float4* Ws4 = reinterpret_cast<float4*>(&Ws[0][0]);
        #pragma unroll
        for (int i = 0; i < 4; ++i) Ws4[t + i * 256] = W4[t + i * 256];
    }
    {   // stage x: float4 global read, SCALAR smem stores (stride 65 -> float4 misaligns)
        const float4* x4 = reinterpret_cast<const float4*>(x);
        #pragma unroll
        for (int i = 0; i < 4; ++i) {
            int f = t + i * 256;
            int r = f >> 4, c4 = f & 15;
            int gr = tileRow + r;
            float4 v = make_float4(0.f, 0.f, 0.f, 0.f);
            if (gr < N) v = x4[(size_t)gr * 16 + c4];
            xs[r][c4 * 4 + 0] = v.x;
            xs[r][c4 * 4 + 1] = v.y;
            xs[r][c4 * 4 + 2] = v.z;
            xs[r][c4 * 4 + 3] = v.w;
        }
    }
    __syncthreads();

    float a[4][4];
    #pragma unroll
    for (int i = 0; i < 4; ++i)
        #pragma unroll
        for (int j = 0; j < 4; ++j) a[i][j] = 0.f;

    const int r0 = ty * 4, c0 = tx * 4;
    #pragma unroll
    for (int k = 0; k < D; ++k) {
        float4 wv = *reinterpret_cast<const float4*>(&Ws[k][c0]);
        float xv0 = xs[r0 + 0][k];
        float xv1 = xs[r0 + 1][k];
        float xv2 = xs[r0 + 2][k];
        float xv3 = xs[r0 + 3][k];
        a[0][0] = fmaf(xv0, wv.x, a[0][0]); a[0][1] = fmaf(xv0, wv.y, a[0][1]);
        a[0][2] = fmaf(xv0, wv.z, a[0][2]); a[0][3] = fmaf(xv0, wv.w, a[0][3]);
        a[1][0] = fmaf(xv1, wv.x, a[1][0]); a[1][1] = fmaf(xv1, wv.y, a[1][1]);
        a[1][2] = fmaf(xv1, wv.z, a[1][2]); a[1][3] = fmaf(xv1, wv.w, a[1][3]);
        a[2][0] = fmaf(xv2, wv.x, a[2][0]); a[2][1] = fmaf(xv2, wv.y, a[2][1]);
        a[2][2] = fmaf(xv2, wv.z, a[2][2]); a[2][3] = fmaf(xv2, wv.w, a[2][3]);
        a[3][0] = fmaf(xv3, wv.x, a[3][0]); a[3][1] = fmaf(xv3, wv.y, a[3][1]);
        a[3][2] = fmaf(xv3, wv.z, a[3][2]); a[3][3] = fmaf(xv3, wv.w, a[3][3]);
    }

    // Store 4 halves (8 B) per row: row = 128 B = 16 uint2; offset tx*8 B aligned.
    #pragma unroll
    for (int i = 0; i < 4; ++i) {
        int gr = tileRow + r0 + i;
        if (gr < N) {
            __half2 h01 = __floats2half2_rn(a[i][0], a[i][1]);
            __half2 h23 = __floats2half2_rn(a[i][2], a[i][3]);
            uint2 pkt;
            pkt.x = *reinterpret_cast<unsigned*>(&h01);
            pkt.y = *reinterpret_cast<unsigned*>(&h23);
            reinterpret_cast<uint2*>(g_support)[(size_t)gr * 16 + tx] = pkt;
        }
    }
}

// ---------------- Kernel 2: histogram of dst ----------------
__global__ void hist_dst(const int* __restrict__ ei, int E)
{
    int e = blockIdx.x * 256 + threadIdx.x;
    if (e < E) atomicAdd(&g_deg[ei[e]], 1);   // result unused -> RED
}

// ---------------- Kernel 3: block-level exclusive scan (1024 elems / 256 thr) --
// Shuffle-based, 2 barriers. Also ZEROES g_deg after reading (restores the
// zero-initialized invariant so hist works on the next graph replay).
__global__ void __launch_bounds__(256) scanA(int n4)   // n4 = N/4 int4 elements
{
    __shared__ int warpOff[8];
    const int tid  = threadIdx.x;
    const int lane = tid & 31;
    const int wid  = tid >> 5;
    const int g4   = blockIdx.x * 256 + tid;

    int4 v = make_int4(0, 0, 0, 0);
    if (g4 < n4) {
        v = reinterpret_cast<int4*>(g_deg)[g4];
        reinterpret_cast<int4*>(g_deg)[g4] = make_int4(0, 0, 0, 0);
    }
    const int s = v.x + v.y + v.z + v.w;

    int inc = s;
    #pragma unroll
    for (int off = 1; off < 32; off <<= 1) {
        int t = __shfl_up_sync(0xffffffffu, inc, off);
        if (lane >= off) inc += t;
    }
    if (lane == 31) warpOff[wid] = inc;
    __syncthreads();
    if (wid == 0) {
        int wv = (lane < 8) ? warpOff[lane] : 0;
        int wi = wv;
        #pragma unroll
        for (int off = 1; off < 8; off <<= 1) {
            int t = __shfl_up_sync(0xffffffffu, wi, off);
            if (lane >= off) wi += t;
        }
        if (lane < 8) warpOff[lane] = wi - wv;       // exclusive warp offsets
        if (lane == 7) g_part[blockIdx.x] = wi;       // block total
    }
    __syncthreads();

    if (g4 < n4) {
        int base = warpOff[wid] + (inc - s);          // exclusive for this thread
        int4 o;
        o.x = base;
        o.y = base + v.x;
        o.z = o.y + v.y;
        o.w = o.z + v.z;
        reinterpret_cast<int4*>(g_ptr)[g4] = o;
    }
}

// ---------------- Kernel 4: scan block totals (1 block, nb <= 128) -------------
__global__ void __launch_bounds__(128) scanB(int nb)
{
    const int lane = threadIdx.x & 31;
    const int wid  = threadIdx.x >> 5;
    __shared__ int warpOff[4];
    int v = (threadIdx.x < nb) ? g_part[threadIdx.x] : 0;
    int inc = v;
    #pragma unroll
    for (int off = 1; off < 32; off <<= 1) {
        int t = __shfl_up_sync(0xffffffffu, inc, off);
        if (lane >= off) inc += t;
    }
    if (lane == 31) warpOff[wid] = inc;
    __syncthreads();
    int woff = 0;
    #pragma unroll
    for (int w = 0; w < 4; ++w) if (w < wid) woff += warpOff[w];
    if (threadIdx.x < nb) g_part[threadIdx.x] = woff + inc - v;  // exclusive
}

// ---------------- Kernel 5: add block offsets; init cursors; sentinel ----------
__global__ void scanC(int N, int E)
{
    int i = blockIdx.x * 256 + threadIdx.x;
    if (i < N) {
        int p = g_ptr[i] + g_part[i >> 10];
        g_ptr[i] = p;
        g_pos[i] = p;
    }
    if (i == 0) g_ptr[N] = E;   // sentinel: deg(node) = ptr[node+1] - ptr[node]
}

// ---------------- Kernel 6: bucket edges by dst ----------------
__global__ void bucket_edges(const int* __restrict__ ei,
                             const float* __restrict__ ew, int E)
{
    int e = blockIdx.x * 256 + threadIdx.x;
    if (e < E) {
        int dst = ei[e];
        int src = ei[E + e];
        float w = ew[e];
        int p = atomicAdd(&g_pos[dst], 1);
        g_csr[p] = make_int2(src, __float_as_int(w));
    }
}

// ---------------- Kernel 7: SpMM over CSR, warp per dst node -------------------
// Lane owns a half2 (4 B) of the 128 B fp16 row; fp32 accumulate; single
// coalesced fp32 write fused with bias. 4-edge unroll for MLP.
__global__ void __launch_bounds__(256) spmm_csr(
    const float* __restrict__ bias,
    float* __restrict__ out,
    int N)
{
    const int node = blockIdx.x * 8 + (threadIdx.x >> 5);
    const int lane = threadIdx.x & 31;
    if (node >= N) return;

    const int start = g_ptr[node];
    const int end   = g_ptr[node + 1];

    const __half2* sup2 = reinterpret_cast<const __half2*>(g_support);
    float accx = 0.f, accy = 0.f;

    int j = start;
    for (; j + 4 <= end; j += 4) {
        int2 m0 = __ldg(&g_csr[j]);
        int2 m1 = __ldg(&g_csr[j + 1]);
        int2 m2 = __ldg(&g_csr[j + 2]);
        int2 m3 = __ldg(&g_csr[j + 3]);
        __half2 h0 = __ldg(&sup2[(size_t)m0.x * 32 + lane]);
        __half2 h1 = __ldg(&sup2[(size_t)m1.x * 32 + lane]);
        __half2 h2 = __ldg(&sup2[(size_t)m2.x * 32 + lane]);
        __half2 h3 = __ldg(&sup2[(size_t)m3.x * 32 + lane]);
        float2 v0 = __half22float2(h0);
        float2 v1 = __half22float2(h1);
        float2 v2 = __half22float2(h2);
        float2 v3 = __half22float2(h3);
        float w0 = __int_as_float(m0.y);
        float w1 = __int_as_float(m1.y);
        float w2 = __int_as_float(m2.y);
        float w3 = __int_as_float(m3.y);
        accx = fmaf(w0, v0.x, accx); accy = fmaf(w0, v0.y, accy);
        accx = fmaf(w1, v1.x, accx); accy = fmaf(w1, v1.y, accy);
        accx = fmaf(w2, v2.x, accx); accy = fmaf(w2, v2.y, accy);
        accx = fmaf(w3, v3.x, accx); accy = fmaf(w3, v3.y, accy);
    }
    for (; j < end; ++j) {
        int2 m = __ldg(&g_csr[j]);
        float2 v = __half22float2(__ldg(&sup2[(size_t)m.x * 32 + lane]));
        float w = __int_as_float(m.y);
        accx = fmaf(w, v.x, accx);
        accy = fmaf(w, v.y, accy);
    }

    float2 b = reinterpret_cast<const float2*>(bias)[lane];
    float2 r = make_float2(accx + b.x, accy + b.y);
    reinterpret_cast<float2*>(out)[(size_t)node * 32 + lane] = r;
}

// ---------------- launch ----------------
extern "C" void kernel_launch(void* const* d_in, const int* in_sizes, int n_in,
                              void* d_out, int out_size)
{
    const float* x    = (const float*)d_in[0];   // [N, 64]
    const int*   ei   = (const int*)  d_in[1];   // [2, E]
    const float* ew   = (const float*)d_in[2];   // [E]
    const float* W    = (const float*)d_in[3];   // [64, 64]
    const float* bias = (const float*)d_in[4];   // [64]
    float* out = (float*)d_out;

    const int N  = in_sizes[0] / D;
    const int E  = in_sizes[2];
    const int n4 = N / 4;                         // N = 100000, divisible by 4
    const int nb = (n4 + 255) / 256;              // 98 scan blocks (1024 elems each)
    const int gE = (E + 255) / 256;
    const int gN = (N + 255) / 256;

    gemm64<<<(N + 63) / 64, 256>>>(x, W, N);
    hist_dst<<<gE, 256>>>(ei, E);
    scanA<<<nb, 256>>>(n4);
    scanB<<<1, 128>>>(nb);
    scanC<<<gN, 256>>>(N, E);
    bucket_edges<<<gE, 256>>>(ei, ew, E);
    spmm_csr<<<(N + 7) / 8, 256>>>(bias, out, N);
}